// round 1
// baseline (speedup 1.0000x reference)
#include <cuda_runtime.h>

#define DD  128
#define N1C 50000
#define N2C 5000

// Scratch (device globals — no allocation allowed)
__device__ float g_agg1[N1C * DD];
__device__ float g_cnt1[N1C];
__device__ float g_h[N1C * DD];
__device__ float g_agg2[N2C * DD];
__device__ float g_cnt2[N2C];

static const int ZERO_TOTAL = N1C * DD + N1C + N2C * DD + N2C;

__global__ void k_zero() {
    const int tot = N1C * DD + N1C + N2C * DD + N2C;
    for (int i = blockIdx.x * blockDim.x + threadIdx.x; i < tot;
         i += gridDim.x * blockDim.x) {
        int j = i;
        if (j < N1C * DD) { g_agg1[j] = 0.f; continue; }
        j -= N1C * DD;
        if (j < N1C)      { g_cnt1[j] = 0.f; continue; }
        j -= N1C;
        if (j < N2C * DD) { g_agg2[j] = 0.f; continue; }
        j -= N2C * DD;
        g_cnt2[j] = 0.f;
    }
}

// One warp per edge: gather 128 floats of the source row, vector-reduce into agg[dst].
template <int L>
__global__ void k_scatter(const float* __restrict__ xext,
                          const int* __restrict__ src,
                          const int* __restrict__ dst, int E) {
    int gw   = (blockIdx.x * blockDim.x + threadIdx.x) >> 5;
    int lane = threadIdx.x & 31;
    if (gw >= E) return;

    const float* xsrc = (L == 1) ? xext : g_h;
    float*       agg  = (L == 1) ? g_agg1 : g_agg2;
    float*       cnt  = (L == 1) ? g_cnt1 : g_cnt2;

    int s = __ldg(src + gw);
    int d = __ldg(dst + gw);

    float4 v = *(const float4*)(xsrc + (size_t)s * DD + lane * 4);
    float* p = agg + (size_t)d * DD + lane * 4;
    asm volatile("red.global.add.v4.f32 [%0], {%1,%2,%3,%4};"
                 :: "l"(p), "f"(v.x), "f"(v.y), "f"(v.z), "f"(v.w)
                 : "memory");
    if (lane == 0) atomicAdd(cnt + d, 1.0f);
}

// Fused SAGE layer: out = relu( (agg/cnt) @ Wl^T + bias + xd @ Wr^T )
// Treated as [M x 256] @ [256 x BN] with K split into (mean | xd) halves.
// BM=64 rows/block, KT=32 k-tile, 256 threads: 16x16 thread grid, 4 x TN microtile.
// Columns are strided (col = tcol + j*16) -> conflict-free scalar LDS on B.
template <int L, int BN, int TN>
__global__ void k_sage(const float* __restrict__ xd_ext,
                       const float* __restrict__ Wl,
                       const float* __restrict__ Wr,
                       const float* __restrict__ bias,
                       float* __restrict__ out_ext, int M) {
    constexpr int BM = 64, KT = 32;
    const float* agg = (L == 1) ? g_agg1 : g_agg2;
    const float* cnt = (L == 1) ? g_cnt1 : g_cnt2;
    const float* xd  = (L == 1) ? xd_ext : g_h;
    float*       out = (L == 1) ? g_h    : out_ext;

    __shared__ float As[BM * (KT + 1)];
    __shared__ float Bs[KT * (BN + 1)];
    __shared__ float inv_s[BM];

    int tid  = threadIdx.x;
    int row0 = blockIdx.x * BM;

    if (tid < BM) {
        int r = row0 + tid;
        inv_s[tid] = (r < M) ? (1.0f / fmaxf(cnt[r], 1.0f)) : 0.f;
    }

    int tcol = tid & 15;   // 16 column groups
    int trow = tid >> 4;   // 16 row groups (4 rows each)

    float acc[4][TN];
#pragma unroll
    for (int i = 0; i < 4; ++i)
#pragma unroll
        for (int j = 0; j < TN; ++j) acc[i][j] = 0.f;

#pragma unroll 1
    for (int kt = 0; kt < 8; ++kt) {
        const bool  first = (kt < 4);
        const int   k0    = (kt & 3) * KT;
        const float* Asrc = first ? agg : xd;
        const float* Bsrc = first ? Wl  : Wr;

        __syncthreads();  // protects smem reuse + inv_s on first iteration

        // A tile: BM*KT = 2048 elems, 8 per thread. kk fastest -> coalesced.
#pragma unroll
        for (int t = 0; t < (BM * KT) / 256; ++t) {
            int idx = tid + t * 256;
            int r = idx >> 5, kk = idx & 31;
            int row = row0 + r;
            float v = 0.f;
            if (row < M) {
                v = Asrc[(size_t)row * 128 + k0 + kk];
                if (first) v *= inv_s[r];
            }
            As[r * (KT + 1) + kk] = v;
        }
        // B tile: BN*KT elems, stored transposed Bs[kk][n].
#pragma unroll
        for (int t = 0; t < (BN * KT) / 256; ++t) {
            int idx = tid + t * 256;
            int n = idx >> 5, kk = idx & 31;
            Bs[kk * (BN + 1) + n] = Bsrc[n * 128 + k0 + kk];
        }
        __syncthreads();

#pragma unroll
        for (int kk = 0; kk < KT; ++kk) {
            float a[4];
#pragma unroll
            for (int i = 0; i < 4; ++i)
                a[i] = As[(trow * 4 + i) * (KT + 1) + kk];
#pragma unroll
            for (int j = 0; j < TN; ++j) {
                float bv = Bs[kk * (BN + 1) + tcol + j * 16];
#pragma unroll
                for (int i = 0; i < 4; ++i)
                    acc[i][j] = fmaf(a[i], bv, acc[i][j]);
            }
        }
    }

#pragma unroll
    for (int i = 0; i < 4; ++i) {
        int row = row0 + trow * 4 + i;
        if (row >= M) continue;
#pragma unroll
        for (int j = 0; j < TN; ++j) {
            int col = tcol + j * 16;
            float v = acc[i][j] + bias[col];
            out[(size_t)row * BN + col] = fmaxf(v, 0.f);
        }
    }
}

extern "C" void kernel_launch(void* const* d_in, const int* in_sizes, int n_in,
                              void* d_out, int out_size) {
    const float* x    = (const float*)d_in[0];
    const float* W1_l = (const float*)d_in[1];
    const float* b1_l = (const float*)d_in[2];
    const float* W1_r = (const float*)d_in[3];
    const float* W2_l = (const float*)d_in[4];
    const float* b2_l = (const float*)d_in[5];
    const float* W2_r = (const float*)d_in[6];
    const int*   src1 = (const int*)d_in[7];
    const int*   dst1 = (const int*)d_in[8];
    const int*   src2 = (const int*)d_in[9];
    const int*   dst2 = (const int*)d_in[10];
    float* out = (float*)d_out;

    int E1 = in_sizes[7];
    int E2 = in_sizes[9];

    // 1) zero accumulators (re-run every replay for determinism)
    k_zero<<<(ZERO_TOTAL + 255) / 256, 256>>>();

    // 2) layer-1 mean-aggregate scatter (warp per edge)
    k_scatter<1><<<(E1 + 7) / 8, 256>>>(x, src1, dst1, E1);

    // 3) layer-1 fused SAGE GEMM -> h [50000 x 128], relu'd
    k_sage<1, 128, 8><<<(N1C + 63) / 64, 256>>>(x, W1_l, W1_r, b1_l, nullptr, N1C);

    // 4) layer-2 scatter over h
    k_scatter<2><<<(E2 + 7) / 8, 256>>>(nullptr, src2, dst2, E2);

    // 5) layer-2 fused SAGE GEMM -> out [5000 x 64], relu'd
    k_sage<2, 64, 4><<<(N2C + 63) / 64, 256>>>(nullptr, W2_l, W2_r, b2_l, out, N2C);
}

// round 2
// speedup vs baseline: 1.4951x; 1.4951x over previous
#include <cuda_runtime.h>

#define DD  128
#define N1C 50000
#define N2C 5000

// Scratch (device globals — no allocation allowed)
__device__ float g_agg1[N1C * DD];
__device__ float g_cnt1[N1C];
__device__ float g_h[N1C * DD];
__device__ float g_agg2[N2C * DD];
__device__ float g_cnt2[N2C];

static const int ZERO_TOTAL = N1C * DD + N1C + N2C * DD + N2C;

__global__ void k_zero() {
    const int tot = N1C * DD + N1C + N2C * DD + N2C;
    for (int i = blockIdx.x * blockDim.x + threadIdx.x; i < tot;
         i += gridDim.x * blockDim.x) {
        int j = i;
        if (j < N1C * DD) { g_agg1[j] = 0.f; continue; }
        j -= N1C * DD;
        if (j < N1C)      { g_cnt1[j] = 0.f; continue; }
        j -= N1C;
        if (j < N2C * DD) { g_agg2[j] = 0.f; continue; }
        j -= N2C * DD;
        g_cnt2[j] = 0.f;
    }
}

// 4 edges per warp: batch 4 independent float4 gathers (MLP=4), then 4 v4 reds.
template <int L>
__global__ void k_scatter(const float* __restrict__ xext,
                          const int* __restrict__ src,
                          const int* __restrict__ dst, int E) {
    constexpr int EPW = 4;
    int warp = (blockIdx.x * blockDim.x + threadIdx.x) >> 5;
    int lane = threadIdx.x & 31;
    int e0   = warp * EPW;
    if (e0 >= E) return;

    const float* xsrc = (L == 1) ? xext : g_h;
    float*       agg  = (L == 1) ? g_agg1 : g_agg2;
    float*       cnt  = (L == 1) ? g_cnt1 : g_cnt2;

    int    d[EPW];
    bool   ok[EPW];
    float4 v[EPW];
#pragma unroll
    for (int e = 0; e < EPW; ++e) {
        int idx = e0 + e;
        ok[e] = idx < E;
        int i2 = ok[e] ? idx : e0;
        int s = __ldg(src + i2);
        d[e]  = __ldg(dst + i2);
        v[e]  = *(const float4*)(xsrc + (size_t)s * DD + lane * 4);
    }
#pragma unroll
    for (int e = 0; e < EPW; ++e) {
        if (!ok[e]) break;
        float* p = agg + (size_t)d[e] * DD + lane * 4;
        asm volatile("red.global.add.v4.f32 [%0], {%1,%2,%3,%4};"
                     :: "l"(p), "f"(v[e].x), "f"(v[e].y), "f"(v[e].z), "f"(v[e].w)
                     : "memory");
        if (lane == 0) atomicAdd(cnt + d[e], 1.0f);
    }
}

// ---------------- tf32 tensor-core layer-1 GEMM ----------------
// g_h = relu( (g_agg1/cnt | xd) [50000 x 256] @ (W1_l | W1_r)^T [256 x 128] + b )
// Block tile 128x128, K=256 in 8 k-tiles of 32. 8 warps as 4(m) x 2(n);
// warp tile 32x64 = 2 m16 x 8 n8 fragments. Smem stride 36 -> conflict-free.
__device__ __forceinline__ unsigned f2tf(float f) {
    unsigned u;
    asm("cvt.rna.tf32.f32 %0, %1;" : "=r"(u) : "f"(f));
    return u;
}

__global__ void __launch_bounds__(256, 2)
k_sage1_mma(const float* __restrict__ xd,
            const float* __restrict__ Wl,
            const float* __restrict__ Wr,
            const float* __restrict__ bias) {
    constexpr int BM = 128, STR = 36;
    __shared__ unsigned As[BM * STR];
    __shared__ unsigned Bs[128 * STR];
    __shared__ float inv_s[BM];

    int tid  = threadIdx.x;
    int row0 = blockIdx.x * BM;

    if (tid < BM) {
        int r = row0 + tid;
        inv_s[tid] = (r < N1C) ? (1.0f / fmaxf(g_cnt1[r], 1.0f)) : 0.f;
    }

    int warp = tid >> 5, lane = tid & 31;
    int wm = warp & 3, wn = warp >> 2;     // 4 m-warps x 2 n-warps
    int lr = lane >> 2, lc = lane & 3;

    float acc[2][8][4];
#pragma unroll
    for (int i = 0; i < 2; ++i)
#pragma unroll
        for (int j = 0; j < 8; ++j)
#pragma unroll
            for (int q = 0; q < 4; ++q) acc[i][j][q] = 0.f;

#pragma unroll 1
    for (int kt = 0; kt < 8; ++kt) {
        const bool  first = (kt < 4);
        const int   k0    = (kt & 3) * 32;
        const float* Asrc = first ? g_agg1 : xd;
        const float* Bsrc = first ? Wl : Wr;

        __syncthreads();  // also covers inv_s on first iteration

        // A tile 128x32: kk fastest -> coalesced global, conflict-free smem
#pragma unroll
        for (int i = 0; i < 16; ++i) {
            int idx = tid + i * 256;
            int r = idx >> 5, kk = idx & 31;
            int row = row0 + r;
            float v = 0.f;
            if (row < N1C) {
                v = Asrc[(size_t)row * 128 + k0 + kk];
                if (first) v *= inv_s[r];
            }
            As[r * STR + kk] = f2tf(v);
        }
        // B tile: weights stored [n][k] (same layout as A)
#pragma unroll
        for (int i = 0; i < 16; ++i) {
            int idx = tid + i * 256;
            int n = idx >> 5, kk = idx & 31;
            Bs[n * STR + kk] = f2tf(Bsrc[n * 128 + k0 + kk]);
        }
        __syncthreads();

#pragma unroll
        for (int ks = 0; ks < 4; ++ks) {
            int kb = ks * 8;
            unsigned a[2][4], b[8][2];
#pragma unroll
            for (int i = 0; i < 2; ++i) {
                int r = wm * 32 + i * 16 + lr;
                a[i][0] = As[r * STR + kb + lc];
                a[i][1] = As[(r + 8) * STR + kb + lc];
                a[i][2] = As[r * STR + kb + lc + 4];
                a[i][3] = As[(r + 8) * STR + kb + lc + 4];
            }
#pragma unroll
            for (int j = 0; j < 8; ++j) {
                int n = wn * 64 + j * 8 + lr;
                b[j][0] = Bs[n * STR + kb + lc];
                b[j][1] = Bs[n * STR + kb + lc + 4];
            }
#pragma unroll
            for (int i = 0; i < 2; ++i)
#pragma unroll
                for (int j = 0; j < 8; ++j)
                    asm volatile(
                        "mma.sync.aligned.m16n8k8.row.col.f32.tf32.tf32.f32 "
                        "{%0,%1,%2,%3}, {%4,%5,%6,%7}, {%8,%9}, {%0,%1,%2,%3};"
                        : "+f"(acc[i][j][0]), "+f"(acc[i][j][1]),
                          "+f"(acc[i][j][2]), "+f"(acc[i][j][3])
                        : "r"(a[i][0]), "r"(a[i][1]), "r"(a[i][2]), "r"(a[i][3]),
                          "r"(b[j][0]), "r"(b[j][1]));
        }
    }

    // Epilogue: bias + relu, write g_h
#pragma unroll
    for (int i = 0; i < 2; ++i) {
#pragma unroll
        for (int j = 0; j < 8; ++j) {
            int col = wn * 64 + j * 8 + 2 * lc;
            float b0 = bias[col], b1 = bias[col + 1];
            int r0 = row0 + wm * 32 + i * 16 + lr;
            if (r0 < N1C) {
                g_h[(size_t)r0 * 128 + col]     = fmaxf(acc[i][j][0] + b0, 0.f);
                g_h[(size_t)r0 * 128 + col + 1] = fmaxf(acc[i][j][1] + b1, 0.f);
            }
            int r1 = r0 + 8;
            if (r1 < N1C) {
                g_h[(size_t)r1 * 128 + col]     = fmaxf(acc[i][j][2] + b0, 0.f);
                g_h[(size_t)r1 * 128 + col + 1] = fmaxf(acc[i][j][3] + b1, 0.f);
            }
        }
    }
}

// ---------------- SIMT fp32 layer-2 GEMM (small) ----------------
__global__ void k_sage2(const float* __restrict__ Wl,
                        const float* __restrict__ Wr,
                        const float* __restrict__ bias,
                        float* __restrict__ out, int M) {
    constexpr int BM = 64, KT = 32, BN = 64, TN = 4;
    __shared__ float As[BM * (KT + 1)];
    __shared__ float Bs[KT * (BN + 1)];
    __shared__ float inv_s[BM];

    int tid  = threadIdx.x;
    int row0 = blockIdx.x * BM;

    if (tid < BM) {
        int r = row0 + tid;
        inv_s[tid] = (r < M) ? (1.0f / fmaxf(g_cnt2[r], 1.0f)) : 0.f;
    }

    int tcol = tid & 15;
    int trow = tid >> 4;

    float acc[4][TN];
#pragma unroll
    for (int i = 0; i < 4; ++i)
#pragma unroll
        for (int j = 0; j < TN; ++j) acc[i][j] = 0.f;

#pragma unroll 1
    for (int kt = 0; kt < 8; ++kt) {
        const bool  first = (kt < 4);
        const int   k0    = (kt & 3) * KT;
        const float* Asrc = first ? g_agg2 : g_h;
        const float* Bsrc = first ? Wl : Wr;

        __syncthreads();
#pragma unroll
        for (int t = 0; t < (BM * KT) / 256; ++t) {
            int idx = tid + t * 256;
            int r = idx >> 5, kk = idx & 31;
            int row = row0 + r;
            float v = 0.f;
            if (row < M) {
                v = Asrc[(size_t)row * 128 + k0 + kk];
                if (first) v *= inv_s[r];
            }
            As[r * (KT + 1) + kk] = v;
        }
#pragma unroll
        for (int t = 0; t < (BN * KT) / 256; ++t) {
            int idx = tid + t * 256;
            int n = idx >> 5, kk = idx & 31;
            Bs[kk * (BN + 1) + n] = Bsrc[n * 128 + k0 + kk];
        }
        __syncthreads();

#pragma unroll
        for (int kk = 0; kk < KT; ++kk) {
            float a[4];
#pragma unroll
            for (int i = 0; i < 4; ++i)
                a[i] = As[(trow * 4 + i) * (KT + 1) + kk];
#pragma unroll
            for (int j = 0; j < TN; ++j) {
                float bv = Bs[kk * (BN + 1) + tcol + j * 16];
#pragma unroll
                for (int i = 0; i < 4; ++i)
                    acc[i][j] = fmaf(a[i], bv, acc[i][j]);
            }
        }
    }

#pragma unroll
    for (int i = 0; i < 4; ++i) {
        int row = row0 + trow * 4 + i;
        if (row >= M) continue;
#pragma unroll
        for (int j = 0; j < TN; ++j) {
            int col = tcol + j * 16;
            float v = acc[i][j] + bias[col];
            out[(size_t)row * BN + col] = fmaxf(v, 0.f);
        }
    }
}

extern "C" void kernel_launch(void* const* d_in, const int* in_sizes, int n_in,
                              void* d_out, int out_size) {
    const float* x    = (const float*)d_in[0];
    const float* W1_l = (const float*)d_in[1];
    const float* b1_l = (const float*)d_in[2];
    const float* W1_r = (const float*)d_in[3];
    const float* W2_l = (const float*)d_in[4];
    const float* b2_l = (const float*)d_in[5];
    const float* W2_r = (const float*)d_in[6];
    const int*   src1 = (const int*)d_in[7];
    const int*   dst1 = (const int*)d_in[8];
    const int*   src2 = (const int*)d_in[9];
    const int*   dst2 = (const int*)d_in[10];
    float* out = (float*)d_out;

    int E1 = in_sizes[7];
    int E2 = in_sizes[9];

    k_zero<<<(ZERO_TOTAL + 255) / 256, 256>>>();

    // warp handles 4 edges; 8 warps/block -> 32 edges/block
    k_scatter<1><<<(E1 + 31) / 32, 256>>>(x, src1, dst1, E1);

    k_sage1_mma<<<(N1C + 127) / 128, 256>>>(x, W1_l, W1_r, b1_l);

    k_scatter<2><<<(E2 + 31) / 32, 256>>>(nullptr, src2, dst2, E2);

    k_sage2<<<(N2C + 63) / 64, 256>>>(W2_l, W2_r, b2_l, out, N2C);
}